// round 11
// baseline (speedup 1.0000x reference)
#include <cuda_runtime.h>
#include <cuda_fp16.h>
#include <stdint.h>
#include <math.h>

#define NG   8
#define NH   512
#define NI   1028
#define NB   128
#define NT   64
#define N3H  1536
#define NTOT (NG*N3H)    // 12288
#define MTOT (NB*NT)     // 8192
#define GH   (NG*NH)     // 4096

// fp16 xproj geometry
#define KPC  1056        // K padded to 33 * 32
#define KT32 33          // k-tiles of 32

// ---- global scratch (__device__: allocation-free rule) ----
__device__ __half g_Xp[(size_t)MTOT * KPC];
__device__ __half g_Wp[(size_t)NTOT * KPC];
__device__ float  g_xproj[(size_t)MTOT * NTOT];
__device__ float  g_h[2][NB * GH];          // fp32 h ping-pong (exact path)
__device__ __half g_hh[2][NB * GH];         // fp16 h planes for MMA
__device__ int    g_sync[NG];

// ---- helpers ----
__device__ __forceinline__ void mma_f16(float* c, const uint32_t* a, const uint32_t* b) {
    asm volatile(
        "mma.sync.aligned.m16n8k16.row.col.f32.f16.f16.f32 "
        "{%0,%1,%2,%3}, {%4,%5,%6,%7}, {%8,%9}, {%0,%1,%2,%3};"
        : "+f"(c[0]), "+f"(c[1]), "+f"(c[2]), "+f"(c[3])
        : "r"(a[0]), "r"(a[1]), "r"(a[2]), "r"(a[3]), "r"(b[0]), "r"(b[1]));
}
__device__ __forceinline__ void ldsm4(uint32_t* r, uint32_t addr) {
    asm volatile("ldmatrix.sync.aligned.m8n8.x4.shared.b16 {%0,%1,%2,%3}, [%4];"
                 : "=r"(r[0]), "=r"(r[1]), "=r"(r[2]), "=r"(r[3]) : "r"(addr));
}
__device__ __forceinline__ uint32_t smem_u32(const void* p) {
    uint32_t a;
    asm("{ .reg .u64 t; cvta.to.shared.u64 t, %1; cvt.u32.u64 %0, t; }" : "=r"(a) : "l"(p));
    return a;
}
__device__ __forceinline__ void cp16(uint32_t dst, const void* src) {
    asm volatile("cp.async.cg.shared.global [%0], [%1], 16;" :: "r"(dst), "l"(src));
}
#define CP_COMMIT()  asm volatile("cp.async.commit_group;" ::: "memory")
#define CP_WAIT(n)   asm volatile("cp.async.wait_group %0;" :: "n"(n) : "memory")

// ---------------------------------------------------------------------------
__global__ void init_h(const float* __restrict__ h0) {
    int i = blockIdx.x * blockDim.x + threadIdx.x;
    if (i < NB * GH) {
        float v = h0[i];
        g_h[0][i]  = v;
        g_hh[0][i] = __float2half_rn(v);
    }
    if (i < NG) g_sync[i] = 0;
}

// Pack X = concat(a,z) -> fp16 plane [MTOT][KPC]
__global__ void pack_x_f16(const float* __restrict__ z, const float* __restrict__ a) {
    size_t idx = (size_t)blockIdx.x * blockDim.x + threadIdx.x;
    if (idx >= (size_t)MTOT * KPC) return;
    int m = (int)(idx / KPC), k = (int)(idx % KPC);
    float v = 0.f;
    if (k < 4)       v = a[m * 4 + k];
    else if (k < NI) v = z[(size_t)m * 1024 + (k - 4)];
    g_Xp[idx] = __float2half_rn(v);
}

// Pack W_ih -> fp16 plane [NTOT][KPC]
__global__ void pack_w_f16(const float* __restrict__ Wih) {
    size_t idx = (size_t)blockIdx.x * blockDim.x + threadIdx.x;
    if (idx >= (size_t)NTOT * KPC) return;
    int n = (int)(idx / KPC), k = (int)(idx % KPC);
    g_Wp[idx] = __float2half_rn((k < NI) ? Wih[(size_t)n * NI + k] : 0.f);
}

// ---------------------------------------------------------------------------
// xproj = X @ W^T + b, fp16, fp32 accum.
// 4-stage cp.async pipeline, prefetch distance 2, ONE sync per k-tile.
// Slot (kt+2)%4 written at iter kt was last read at iter kt-2 -> no race
// with warps still finishing iter kt-1.
// ---------------------------------------------------------------------------
#define ROWB   80
#define PLANE  (128 * ROWB)      // 10240 B
#define STG    (2 * PLANE)       // 20480 B per stage (A+B planes)
#define XS_SMEM (4 * STG)        // 81920 B

__global__ __launch_bounds__(256) void xproj_f16(const float* __restrict__ bih) {
    extern __shared__ char smem[];
    const uint32_t sb = smem_u32(smem);
    const int tid = threadIdx.x, lane = tid & 31, warp = tid >> 5;
    const int m0 = blockIdx.y * 128, n0 = blockIdx.x * 128;
    const int wm = (warp & 1) * 64, wn = (warp >> 1) * 32;
    const int grp = lane >> 2, tg = lane & 3;

    float c[4][4][4] = {};

    auto stage = [&](int kt) {
        const uint32_t dst0 = sb + (kt & 3) * STG;
        #pragma unroll
        for (int u = 0; u < 4; ++u) {
            const int i = tid + u * 256;
            const int s = i >> 9;
            const int r = (i >> 2) & 127;
            const int ch = i & 3;
            const char* src = s
                ? (const char*)&g_Wp[(size_t)(n0 + r) * KPC]
                : (const char*)&g_Xp[(size_t)(m0 + r) * KPC];
            cp16(dst0 + s * PLANE + r * ROWB + ch * 16, src + kt * 64 + ch * 16);
        }
        CP_COMMIT();
    };

    stage(0);
    stage(1);

    const int rowA = wm + (lane & 15);
    const int kAoff = (lane & 16) ? 16 : 0;
    const int rowB = wn + (lane & 7) + ((lane & 16) ? 8 : 0);
    const int kBoff = (lane & 8) ? 16 : 0;

    for (int kt = 0; kt < KT32; ++kt) {
        if (kt + 2 < KT32) { stage(kt + 2); CP_WAIT(2); }
        else if (kt + 1 < KT32) { CP_WAIT(1); }
        else { CP_WAIT(0); }
        __syncthreads();

        const uint32_t base = sb + (kt & 3) * STG;
        #pragma unroll
        for (int ks = 0; ks < 2; ++ks) {
            uint32_t ah[4][4], bh[4][2];
            #pragma unroll
            for (int mi = 0; mi < 4; ++mi)
                ldsm4(ah[mi], base + (rowA + mi * 16) * ROWB + ks * 32 + kAoff);
            #pragma unroll
            for (int np = 0; np < 2; ++np) {
                uint32_t t4[4];
                ldsm4(t4, base + PLANE + (rowB + np * 16) * ROWB + ks * 32 + kBoff);
                bh[np * 2][0] = t4[0]; bh[np * 2][1] = t4[1];
                bh[np * 2 + 1][0] = t4[2]; bh[np * 2 + 1][1] = t4[3];
            }
            #pragma unroll
            for (int mi = 0; mi < 4; ++mi)
                #pragma unroll
                for (int nj = 0; nj < 4; ++nj)
                    mma_f16(c[mi][nj], ah[mi], bh[nj]);
        }
    }

    #pragma unroll
    for (int nj = 0; nj < 4; ++nj) {
        const int col = n0 + wn + nj * 8 + 2 * tg;
        const float b0v = bih[col], b1v = bih[col + 1];
        #pragma unroll
        for (int mi = 0; mi < 4; ++mi) {
            const int r0 = m0 + wm + mi * 16 + grp;
            float2 v0 = make_float2(c[mi][nj][0] + b0v, c[mi][nj][1] + b1v);
            float2 v1 = make_float2(c[mi][nj][2] + b0v, c[mi][nj][3] + b1v);
            *(float2*)&g_xproj[(size_t)r0 * NTOT + col]       = v0;
            *(float2*)&g_xproj[(size_t)(r0 + 8) * NTOT + col] = v1;
        }
    }
}

// ---------------------------------------------------------------------------
// Persistent recurrence, sync-free mainloop.
// R10 changes: (a) epilogue's g_xproj/h_old loads hoisted to step head so
// their DRAM latency overlaps the mainloop; (b) `out` stores moved after the
// group barrier (private data -> out of the fenced set, overlaps next step).
// ---------------------------------------------------------------------------
#define W_STRIDE 1040
#define SMEM_GRU (96 * W_STRIDE)        // 99840

__global__ __launch_bounds__(256) void gru_persistent(
    const float* __restrict__ Whh, const float* __restrict__ bhh,
    float* __restrict__ out)
{
    extern __shared__ char sm[];
    const uint32_t sb = smem_u32(sm);

    const int tid  = threadIdx.x;
    const int g    = blockIdx.x >> 4;
    const int c0   = (blockIdx.x & 15) * 32;
    const int warp = tid >> 5, lane = tid & 31;
    const int grp  = lane >> 2, tg = lane & 3;
    const int wm   = warp * 16;

    // ---- Fill W plane once (rows n = gate*32 + cl, cols k) ----
    for (int idx = tid; idx < 96 * 512; idx += 256) {
        const int n = idx >> 9, k = idx & 511;
        const float v = Whh[(size_t)(g * N3H + (n >> 5) * NH + c0 + (n & 31)) * NH + k];
        *(__half*)(sm + n * W_STRIDE + k * 2) = __float2half_rn(v);
    }

    // ---- Loop-invariant biases ----
    float bias[3][4][2];
    #pragma unroll
    for (int gate = 0; gate < 3; ++gate)
        #pragma unroll
        for (int j = 0; j < 4; ++j) {
            bias[gate][j][0] = bhh[g * N3H + gate * NH + c0 + j * 8 + 2 * tg];
            bias[gate][j][1] = bhh[g * N3H + gate * NH + c0 + j * 8 + 2 * tg + 1];
        }
    __syncthreads();

    const int rB  = (lane & 7) + ((lane & 16) ? 8 : 0);
    const uint32_t bko = (lane & 8) ? 16 : 0;

    const size_t aRow0 = (size_t)(wm + grp) * GH + g * NH + 2 * tg;
    const size_t aRow1 = aRow0 + (size_t)8 * GH;

    for (int t = 0; t < NT; ++t) {
        const __half* __restrict__ hhp = g_hh[t & 1];
        const float* __restrict__ hin = g_h[t & 1];

        auto lda = [&](uint32_t* f, int kc) {
            const int ko = kc * 16;
            f[0] = __ldcg((const uint32_t*)(hhp + aRow0 + ko));
            f[1] = __ldcg((const uint32_t*)(hhp + aRow1 + ko));
            f[2] = __ldcg((const uint32_t*)(hhp + aRow0 + ko + 8));
            f[3] = __ldcg((const uint32_t*)(hhp + aRow1 + ko + 8));
        };

        uint32_t af[2][4];
        lda(af[0], 0);
        lda(af[1], 1);

        // ---- Hoisted epilogue operands: overlap mainloop with their latency
        float2 xv[3][4][2], hv[4][2];
        #pragma unroll
        for (int j = 0; j < 4; ++j)
            #pragma unroll
            for (int r = 0; r < 2; ++r) {
                const int row = wm + grp + r * 8;
                const int col = c0 + j * 8 + 2 * tg;
                hv[j][r] = __ldcg((const float2*)&hin[(size_t)row * GH + g * NH + col]);
                const size_t xb = (size_t)(row * NT + t) * NTOT + g * N3H;
                #pragma unroll
                for (int gate = 0; gate < 3; ++gate)
                    xv[gate][j][r] = *(const float2*)&g_xproj[xb + gate * NH + col];
            }

        float acc[12][4] = {};

        #pragma unroll 4
        for (int kc = 0; kc < 32; ++kc) {
            uint32_t ah[4];
            ah[0] = af[kc & 1][0]; ah[1] = af[kc & 1][1];
            ah[2] = af[kc & 1][2]; ah[3] = af[kc & 1][3];
            if (kc < 30) lda(af[kc & 1], kc + 2);

            const uint32_t kb = kc * 32 + bko;
            #pragma unroll
            for (int jp = 0; jp < 6; ++jp) {
                uint32_t bh4[4];
                ldsm4(bh4, sb + (jp * 16 + rB) * W_STRIDE + kb);
                mma_f16(acc[jp * 2],     ah, bh4);
                mma_f16(acc[jp * 2 + 1], ah, bh4 + 2);
            }
        }

        // ---- Gate epilogue: write h (fp32 + fp16) only; keep out in regs
        float* __restrict__ hout = g_h[(t + 1) & 1];
        __half* __restrict__ nhh = g_hh[(t + 1) & 1];
        float2 outv[4][2];

        #pragma unroll
        for (int j = 0; j < 4; ++j)
            #pragma unroll
            for (int r = 0; r < 2; ++r) {
                const int row = wm + grp + r * 8;
                const int col = c0 + j * 8 + 2 * tg;
                const size_t hidx = (size_t)row * GH + g * NH + col;
                float2 hn2;
                #pragma unroll
                for (int p = 0; p < 2; ++p) {
                    const float hr = acc[j    ][r * 2 + p] + bias[0][j][p];
                    const float hz = acc[j + 4][r * 2 + p] + bias[1][j][p];
                    const float hnv= acc[j + 8][r * 2 + p] + bias[2][j][p];
                    const float xr = p ? xv[0][j][r].y : xv[0][j][r].x;
                    const float xz = p ? xv[1][j][r].y : xv[1][j][r].x;
                    const float xn = p ? xv[2][j][r].y : xv[2][j][r].x;
                    const float ho = p ? hv[j][r].y : hv[j][r].x;
                    const float rr = 1.f / (1.f + __expf(-(xr + hr)));
                    const float uu = 1.f / (1.f + __expf(-(xz + hz)));
                    const float nn = tanhf(xn + rr * hnv);
                    const float hw = (1.f - uu) * nn + uu * ho;
                    if (p == 0) hn2.x = hw; else hn2.y = hw;
                }
                *(float2*)&hout[hidx] = hn2;
                __half2 h2;
                h2.x = __float2half_rn(hn2.x);
                h2.y = __float2half_rn(hn2.y);
                *(__half2*)&nhh[hidx] = h2;
                outv[j][r] = hn2;
            }

        // ---- group barrier: 16 CTAs of block g (fences only h writes) ----
        __threadfence();
        __syncthreads();
        if (tid == 0) {
            atomicAdd(&g_sync[g], 1);
            const int target = 16 * (t + 1);
            while (*(volatile int*)&g_sync[g] < target) { __nanosleep(32); }
        }
        __syncthreads();

        // ---- deferred out stores: overlap next step's mainloop ----
        #pragma unroll
        for (int j = 0; j < 4; ++j)
            #pragma unroll
            for (int r = 0; r < 2; ++r) {
                const int row = wm + grp + r * 8;
                const int col = c0 + j * 8 + 2 * tg;
                *(float2*)&out[(size_t)(row * NT + t) * GH + g * NH + col] = outv[j][r];
            }
    }
}

// ---------------------------------------------------------------------------
extern "C" void kernel_launch(void* const* d_in, const int* in_sizes, int n_in,
                              void* d_out, int out_size) {
    const float* z   = (const float*)d_in[0];
    const float* a   = (const float*)d_in[1];
    const float* h   = (const float*)d_in[2];
    const float* Wih = (const float*)d_in[3];
    const float* Whh = (const float*)d_in[4];
    const float* bih = (const float*)d_in[5];
    const float* bhh = (const float*)d_in[6];
    float* out = (float*)d_out;

    init_h<<<(NB * GH + 255) / 256, 256>>>(h);

    {
        size_t nx = (size_t)MTOT * KPC;
        pack_x_f16<<<(int)((nx + 255) / 256), 256>>>(z, a);
        size_t nw = (size_t)NTOT * KPC;
        pack_w_f16<<<(int)((nw + 255) / 256), 256>>>(Wih);
    }

    cudaFuncSetAttribute(xproj_f16, cudaFuncAttributeMaxDynamicSharedMemorySize, XS_SMEM);
    dim3 grid(NTOT / 128, MTOT / 128);   // (96, 64)
    xproj_f16<<<grid, 256, XS_SMEM>>>(bih);

    cudaFuncSetAttribute(gru_persistent, cudaFuncAttributeMaxDynamicSharedMemorySize, SMEM_GRU);
    gru_persistent<<<128, 256, SMEM_GRU>>>(Whh, bhh, out);
}